// round 1
// baseline (speedup 1.0000x reference)
#include <cuda_runtime.h>
#include <cstdint>

#define B_ROWS 65536
#define D_IN   784
#define D_H    1024
#define N_CLS  10
#define BN_EPS 1e-5f

// ---------------- device scratch (no dynamic allocation allowed) -------------
__device__ float    g_Sf[D_H * D_IN];                    // sign(w1) as fp32, [1024,784]
__device__ float    g_h[(size_t)B_ROWS * D_H];           // hidden activations, 268 MB
__device__ float    g_sum[D_H];
__device__ float    g_sumsq[D_H];
__device__ float    g_A[D_H];                            // gamma * invstd
__device__ float    g_Bc[D_H];                           // beta - A*mu
__device__ unsigned g_tbits[N_CLS][32];                  // packed sign(w2) bits

// ---------------- prep: binarize w1, pack w2 signs, zero stats ---------------
__global__ void prep_kernel(const float* __restrict__ w1,
                            const float* __restrict__ w2) {
    int i = blockIdx.x * blockDim.x + threadIdx.x;
    if (i < D_H * D_IN) {
        float v = w1[i];
        g_Sf[i] = (v > 0.f) ? 1.f : (v < 0.f ? -1.f : 0.f);
    }
    if (i < D_H) { g_sum[i] = 0.f; g_sumsq[i] = 0.f; }
    if (i < N_CLS * 32) {
        int c = i >> 5, g = i & 31;
        unsigned w = 0;
        #pragma unroll
        for (int l = 0; l < 32; l++) {
            float v = w2[c * D_H + g * 32 + l];
            if (v > 0.f) w |= (1u << l);
        }
        g_tbits[c][g] = w;
    }
}

// ---------------- GEMM1: h = x @ sign(w1)^T  (fp32, tiled SIMT) --------------
// C[M=65536, N=1024] = X[M,784] * Sf[N,784]^T   (both K-major)
// Block tile 128x128, K-tile 16, 256 threads, 8x8 per thread.
__global__ __launch_bounds__(256, 2)
void gemm1_kernel(const float* __restrict__ X) {
    __shared__ float As[16][128];
    __shared__ float Bs[16][128];

    const int bm = blockIdx.x;          // 0..511
    const int bn = blockIdx.y;          // 0..7
    const int tid = threadIdx.x;
    const int tx = tid & 15;            // 0..15 -> 8 cols each
    const int ty = tid >> 4;            // 0..15 -> 8 rows each

    float acc[8][8];
    #pragma unroll
    for (int i = 0; i < 8; i++)
        #pragma unroll
        for (int j = 0; j < 8; j++) acc[i][j] = 0.f;

    const float* Xb = X    + (size_t)bm * 128 * D_IN;
    const float* Wb = g_Sf + (size_t)bn * 128 * D_IN;

    const int lr = tid >> 2;            // 0..63 (row group)
    const int lc = (tid & 3) * 4;       // 0,4,8,12 (k offset within k-tile)

    for (int k0 = 0; k0 < D_IN; k0 += 16) {
        #pragma unroll
        for (int r = 0; r < 2; r++) {
            int row = lr + r * 64;
            float4 a = *(const float4*)(Xb + (size_t)row * D_IN + k0 + lc);
            As[lc + 0][row] = a.x; As[lc + 1][row] = a.y;
            As[lc + 2][row] = a.z; As[lc + 3][row] = a.w;
            float4 b = *(const float4*)(Wb + (size_t)row * D_IN + k0 + lc);
            Bs[lc + 0][row] = b.x; Bs[lc + 1][row] = b.y;
            Bs[lc + 2][row] = b.z; Bs[lc + 3][row] = b.w;
        }
        __syncthreads();

        #pragma unroll
        for (int k = 0; k < 16; k++) {
            float a[8], b[8];
            #pragma unroll
            for (int i = 0; i < 8; i++) a[i] = As[k][ty * 8 + i];
            #pragma unroll
            for (int j = 0; j < 8; j++) b[j] = Bs[k][tx * 8 + j];
            #pragma unroll
            for (int i = 0; i < 8; i++)
                #pragma unroll
                for (int j = 0; j < 8; j++)
                    acc[i][j] = fmaf(a[i], b[j], acc[i][j]);
        }
        __syncthreads();
    }

    float* H = g_h + (size_t)(bm * 128) * D_H + bn * 128;
    #pragma unroll
    for (int i = 0; i < 8; i++) {
        int r = ty * 8 + i;
        #pragma unroll
        for (int j = 0; j < 8; j += 4) {
            float4 v = make_float4(acc[i][j], acc[i][j+1], acc[i][j+2], acc[i][j+3]);
            *(float4*)(H + (size_t)r * D_H + tx * 8 + j) = v;
        }
    }
}

// ---------------- column stats: sum & sumsq over batch -----------------------
// grid (4, 64): block handles 256 consecutive columns x 1024 rows (coalesced).
__global__ void stats_kernel() {
    int c = blockIdx.x * 256 + threadIdx.x;        // 0..1023
    size_t r0 = (size_t)blockIdx.y * 1024;
    const float* p = g_h + r0 * D_H + c;
    float s0 = 0.f, s1 = 0.f, q0 = 0.f, q1 = 0.f;
    for (int r = 0; r < 1024; r += 2) {
        float v0 = p[(size_t)r * D_H];
        float v1 = p[(size_t)(r + 1) * D_H];
        s0 += v0; q0 = fmaf(v0, v0, q0);
        s1 += v1; q1 = fmaf(v1, v1, q1);
    }
    atomicAdd(&g_sum[c], s0 + s1);
    atomicAdd(&g_sumsq[c], q0 + q1);
}

// ---------------- finalize BN affine params ----------------------------------
__global__ void finalize_kernel(const float* __restrict__ gamma,
                                const float* __restrict__ beta) {
    int j = blockIdx.x * blockDim.x + threadIdx.x;
    if (j < D_H) {
        float mu  = g_sum[j] * (1.f / B_ROWS);
        float var = g_sumsq[j] * (1.f / B_ROWS) - mu * mu;
        float inv = rsqrtf(var + BN_EPS);
        float A   = gamma[j] * inv;
        g_A[j]  = A;
        g_Bc[j] = beta[j] - A * mu;
    }
}

// ---------------- output: sign(bn(h)) @ sign(w2)^T via xor-popcount ----------
// One warp per batch row. word g, bit `lane` <-> column g*32+lane.
__global__ __launch_bounds__(256)
void out_kernel(float* __restrict__ out) {
    int warp = (blockIdx.x * 256 + threadIdx.x) >> 5;
    int lane = threadIdx.x & 31;
    if (warp >= B_ROWS) return;

    const float* hrow = g_h + (size_t)warp * D_H;

    unsigned myword = 0;
    int adj[N_CLS];
    #pragma unroll
    for (int c = 0; c < N_CLS; c++) adj[c] = 0;

    for (int g = 0; g < 32; g++) {
        int col = g * 32 + lane;
        float v = fmaf(g_A[col], hrow[col], g_Bc[col]);
        unsigned w = __ballot_sync(0xffffffffu, v > 0.f);
        if (lane == g) myword = w;
        if (v == 0.f) {
            // we counted this column as -1; true contribution is 0 -> add back t
            #pragma unroll
            for (int c = 0; c < N_CLS; c++)
                adj[c] += ((g_tbits[c][g] >> lane) & 1u) ? 1 : -1;
        }
    }

    #pragma unroll
    for (int c = 0; c < N_CLS; c++) {
        unsigned x = myword ^ g_tbits[c][lane];
        int s = 32 - 2 * __popc(x) + adj[c];
        s = __reduce_add_sync(0xffffffffu, s);
        if (lane == 0) out[(size_t)warp * N_CLS + c] = (float)s;
    }
}

// ---------------- launch ------------------------------------------------------
extern "C" void kernel_launch(void* const* d_in, const int* in_sizes, int n_in,
                              void* d_out, int out_size) {
    const float* x     = (const float*)d_in[0];
    const float* w1    = (const float*)d_in[1];
    const float* gamma = (const float*)d_in[2];
    const float* beta  = (const float*)d_in[3];
    const float* w2    = (const float*)d_in[4];
    float* out = (float*)d_out;

    prep_kernel<<<(D_H * D_IN + 255) / 256, 256>>>(w1, w2);

    dim3 g1(B_ROWS / 128, D_H / 128);
    gemm1_kernel<<<g1, 256>>>(x);

    dim3 gs(D_H / 256, 64);
    stats_kernel<<<gs, 256>>>();

    finalize_kernel<<<4, 256>>>(gamma, beta);

    out_kernel<<<(B_ROWS * 32) / 256, 256>>>(out);
}

// round 3
// speedup vs baseline: 1.9439x; 1.9439x over previous
#include <cuda_runtime.h>
#include <cuda_bf16.h>
#include <cstdint>

#define B_ROWS 65536
#define D_IN   784
#define D_H    1024
#define N_CLS  10
#define BN_EPS 1e-5f
#define KP     2368            // padded K = 3*784 (=2352) + 16 zeros
#define BK     32
#define NIT    (KP / BK)       // 74
#define BMT    128
#define BNT    128
#define SROW   40              // smem row stride in bf16 (80 bytes), conflict-free
#define STAGE_B (BMT * SROW * 2 * 2)   // A + B per stage = 20480 bytes
#define NSTAGE 3

// ---------------- device scratch ---------------------------------------------
__device__ __nv_bfloat16 g_xb[(size_t)B_ROWS * KP];   // x split into 3 bf16 planes
__device__ __nv_bfloat16 g_sb[(size_t)D_H * KP];      // sign(w1) tiled 3x, bf16
__device__ float    g_h[(size_t)B_ROWS * D_H];
__device__ float    g_sum[D_H];
__device__ float    g_sumsq[D_H];
__device__ float    g_A[D_H];
__device__ float    g_Bc[D_H];
__device__ unsigned g_tbits[N_CLS][32];

// ---------------- PTX helpers -------------------------------------------------
__device__ __forceinline__ uint32_t s2u(const void* p) {
    uint32_t a;
    asm("{ .reg .u64 t; cvta.to.shared.u64 t, %1; cvt.u32.u64 %0, t; }" : "=r"(a) : "l"(p));
    return a;
}
__device__ __forceinline__ void cpa16(uint32_t s, const void* g) {
    asm volatile("cp.async.cg.shared.global [%0], [%1], 16;" :: "r"(s), "l"(g) : "memory");
}
__device__ __forceinline__ void cp_commit() {
    asm volatile("cp.async.commit_group;" ::: "memory");
}
__device__ __forceinline__ void ldmA(uint32_t* a, uint32_t addr) {
    asm volatile("ldmatrix.sync.aligned.m8n8.x4.shared.b16 {%0,%1,%2,%3}, [%4];"
                 : "=r"(a[0]), "=r"(a[1]), "=r"(a[2]), "=r"(a[3]) : "r"(addr));
}
__device__ __forceinline__ void ldmB(uint32_t* b, uint32_t addr) {
    asm volatile("ldmatrix.sync.aligned.m8n8.x2.shared.b16 {%0,%1}, [%2];"
                 : "=r"(b[0]), "=r"(b[1]) : "r"(addr));
}
__device__ __forceinline__ void mma16816(float* c, const uint32_t* a, const uint32_t* b) {
    asm volatile("mma.sync.aligned.m16n8k16.row.col.f32.bf16.bf16.f32 "
                 "{%0,%1,%2,%3}, {%4,%5,%6,%7}, {%8,%9}, {%0,%1,%2,%3};"
                 : "+f"(c[0]), "+f"(c[1]), "+f"(c[2]), "+f"(c[3])
                 : "r"(a[0]), "r"(a[1]), "r"(a[2]), "r"(a[3]), "r"(b[0]), "r"(b[1]));
}

// ---------------- prep: bf16 sign(w1) tiled 3x, pack w2, zero stats ----------
__global__ void prep_kernel(const float* __restrict__ w1,
                            const float* __restrict__ w2) {
    int i = blockIdx.x * blockDim.x + threadIdx.x;
    if (i < D_H * KP) {
        int n = i / KP, k = i % KP;
        float s = 0.f;
        if (k < 3 * D_IN) {
            float v = w1[n * D_IN + (k % D_IN)];
            s = (v > 0.f) ? 1.f : (v < 0.f ? -1.f : 0.f);
        }
        g_sb[i] = __float2bfloat16(s);
    }
    if (i < D_H) { g_sum[i] = 0.f; g_sumsq[i] = 0.f; }
    if (i < N_CLS * 32) {
        int c = i >> 5, g = i & 31;
        unsigned w = 0;
        #pragma unroll
        for (int l = 0; l < 32; l++) {
            float v = w2[c * D_H + g * 32 + l];
            if (v > 0.f) w |= (1u << l);
        }
        g_tbits[c][g] = w;
    }
}

// ---------------- convert: x -> 3 bf16 planes (hi/mid/lo), K-concatenated ----
__global__ void convert_kernel(const float* __restrict__ x) {
    size_t i = (size_t)blockIdx.x * blockDim.x + threadIdx.x;
    if (i >= (size_t)B_ROWS * (D_IN / 4)) return;
    size_t m = i / (D_IN / 4);
    int k4 = (int)(i % (D_IN / 4)) * 4;
    float4 v = *(const float4*)(x + m * D_IN + k4);
    float f[4] = {v.x, v.y, v.z, v.w};
    __nv_bfloat162 hi2[2], mid2[2], lo2[2];
    #pragma unroll
    for (int j = 0; j < 2; j++) {
        __nv_bfloat16 h0 = __float2bfloat16(f[2*j]);
        __nv_bfloat16 h1 = __float2bfloat16(f[2*j+1]);
        float r0 = f[2*j]   - __bfloat162float(h0);
        float r1 = f[2*j+1] - __bfloat162float(h1);
        __nv_bfloat16 m0 = __float2bfloat16(r0);
        __nv_bfloat16 m1 = __float2bfloat16(r1);
        float s0 = r0 - __bfloat162float(m0);
        float s1 = r1 - __bfloat162float(m1);
        hi2[j]  = __nv_bfloat162(h0, h1);
        mid2[j] = __nv_bfloat162(m0, m1);
        lo2[j]  = __nv_bfloat162(__float2bfloat16(s0), __float2bfloat16(s1));
    }
    __nv_bfloat162* row = (__nv_bfloat162*)(g_xb + m * KP);
    int p = k4 >> 1;
    row[p]            = hi2[0];  row[p + 1]            = hi2[1];
    row[p + D_IN/2]   = mid2[0]; row[p + D_IN/2 + 1]   = mid2[1];
    row[p + D_IN]     = lo2[0];  row[p + D_IN + 1]     = lo2[1];
}

__global__ void pad_kernel() {
    int i = blockIdx.x * blockDim.x + threadIdx.x;
    if (i < B_ROWS * 2) {
        size_t row = (size_t)(i >> 1);
        uint4 z = make_uint4(0, 0, 0, 0);
        *(uint4*)((char*)(g_xb + row * KP + 3 * D_IN) + (i & 1) * 16) = z;
    }
}

// ---------------- GEMM1: h = Xsplit @ Sb^T via mma.sync bf16 ------------------
// CTA tile 128x128, 8 warps (2x4), warp tile 64x32, BK=32, 3-stage cp.async.
__global__ __launch_bounds__(256)
void gemm1_kernel() {
    extern __shared__ char smem[];
    const uint32_t sb = s2u(smem);
    const int tid = threadIdx.x, wid = tid >> 5, lane = tid & 31;
    const int bn = blockIdx.x, bm = blockIdx.y;
    const int warp_m = wid >> 2, warp_n = wid & 3;     // 2 x 4

    const __nv_bfloat16* Ab = g_xb + (size_t)bm * BMT * KP;
    const __nv_bfloat16* Bb = g_sb + (size_t)bn * BNT * KP;

    // per-thread load slots: 2 for A, 2 for B (16B each)
    auto load_stage = [&](int it, int stage) {
        uint32_t sA = sb + stage * STAGE_B;
        uint32_t sBs = sA + BMT * SROW * 2;
        int k0 = it * BK;
        #pragma unroll
        for (int j = 0; j < 2; j++) {
            int idx = tid + j * 256;                   // 0..511
            int row = idx >> 2, q = idx & 3;           // 4 x 16B per 64B row
            cpa16(sA + row * (SROW * 2) + q * 16,
                  (const char*)(Ab + (size_t)row * KP + k0) + q * 16);
            cpa16(sBs + row * (SROW * 2) + q * 16,
                  (const char*)(Bb + (size_t)row * KP + k0) + q * 16);
        }
        cp_commit();
    };

    float acc[4][4][4];
    #pragma unroll
    for (int i = 0; i < 4; i++)
        #pragma unroll
        for (int j = 0; j < 4; j++)
            #pragma unroll
            for (int r = 0; r < 4; r++) acc[i][j][r] = 0.f;

    load_stage(0, 0);
    load_stage(1, 1);

    for (int i = 0; i < NIT; i++) {
        asm volatile("cp.async.wait_group 1;" ::: "memory");
        __syncthreads();
        if (i + 2 < NIT) load_stage(i + 2, (i + 2) % NSTAGE);
        else cp_commit();

        uint32_t sA = sb + (i % NSTAGE) * STAGE_B;
        uint32_t sBs = sA + BMT * SROW * 2;

        #pragma unroll
        for (int ks = 0; ks < 2; ks++) {               // two k16 steps
            uint32_t afrag[4][4], bfrag[4][2];
            #pragma unroll
            for (int mt = 0; mt < 4; mt++) {
                int row = warp_m * 64 + mt * 16 + (lane & 15);
                uint32_t addr = sA + row * (SROW * 2) + ks * 32 + (lane >> 4) * 16;
                ldmA(afrag[mt], addr);
            }
            #pragma unroll
            for (int nt = 0; nt < 4; nt++) {
                int row = warp_n * 32 + nt * 8 + (lane & 7);
                uint32_t addr = sBs + row * (SROW * 2) + ks * 32 + ((lane >> 3) & 1) * 16;
                ldmB(bfrag[nt], addr);
            }
            #pragma unroll
            for (int mt = 0; mt < 4; mt++)
                #pragma unroll
                for (int nt = 0; nt < 4; nt++)
                    mma16816(acc[mt][nt], afrag[mt], bfrag[nt]);
        }
        __syncthreads();
    }

    // epilogue: write fp32 h
    float* Hb = g_h + (size_t)(bm * BMT) * D_H + bn * BNT;
    #pragma unroll
    for (int mt = 0; mt < 4; mt++) {
        int r0 = warp_m * 64 + mt * 16 + (lane >> 2);
        #pragma unroll
        for (int nt = 0; nt < 4; nt++) {
            int c = warp_n * 32 + nt * 8 + (lane & 3) * 2;
            *(float2*)(Hb + (size_t)r0 * D_H + c)       = make_float2(acc[mt][nt][0], acc[mt][nt][1]);
            *(float2*)(Hb + (size_t)(r0 + 8) * D_H + c) = make_float2(acc[mt][nt][2], acc[mt][nt][3]);
        }
    }
}

// ---------------- column stats over batch ------------------------------------
__global__ void stats_kernel() {
    int c = blockIdx.x * 256 + threadIdx.x;
    size_t r0 = (size_t)blockIdx.y * 1024;
    const float* p = g_h + r0 * D_H + c;
    float s0 = 0.f, s1 = 0.f, q0 = 0.f, q1 = 0.f;
    for (int r = 0; r < 1024; r += 2) {
        float v0 = p[(size_t)r * D_H];
        float v1 = p[(size_t)(r + 1) * D_H];
        s0 += v0; q0 = fmaf(v0, v0, q0);
        s1 += v1; q1 = fmaf(v1, v1, q1);
    }
    atomicAdd(&g_sum[c], s0 + s1);
    atomicAdd(&g_sumsq[c], q0 + q1);
}

__global__ void finalize_kernel(const float* __restrict__ gamma,
                                const float* __restrict__ beta) {
    int j = blockIdx.x * blockDim.x + threadIdx.x;
    if (j < D_H) {
        float mu  = g_sum[j] * (1.f / B_ROWS);
        float var = g_sumsq[j] * (1.f / B_ROWS) - mu * mu;
        float inv = rsqrtf(var + BN_EPS);
        float A   = gamma[j] * inv;
        g_A[j]  = A;
        g_Bc[j] = beta[j] - A * mu;
    }
}

// ---------------- output: sign(bn(h)) @ sign(w2)^T via xor-popcount ----------
__global__ __launch_bounds__(256)
void out_kernel(float* __restrict__ out) {
    int warp = (blockIdx.x * 256 + threadIdx.x) >> 5;
    int lane = threadIdx.x & 31;
    if (warp >= B_ROWS) return;

    const float* hrow = g_h + (size_t)warp * D_H;
    unsigned myword = 0;
    int adj[N_CLS];
    #pragma unroll
    for (int c = 0; c < N_CLS; c++) adj[c] = 0;

    for (int g = 0; g < 32; g++) {
        int col = g * 32 + lane;
        float v = fmaf(g_A[col], hrow[col], g_Bc[col]);
        unsigned w = __ballot_sync(0xffffffffu, v > 0.f);
        if (lane == g) myword = w;
        if (v == 0.f) {
            #pragma unroll
            for (int c = 0; c < N_CLS; c++)
                adj[c] += ((g_tbits[c][g] >> lane) & 1u) ? 1 : -1;
        }
    }
    #pragma unroll
    for (int c = 0; c < N_CLS; c++) {
        unsigned x = myword ^ g_tbits[c][lane];
        int s = 32 - 2 * __popc(x) + adj[c];
        s = __reduce_add_sync(0xffffffffu, s);
        if (lane == 0) out[(size_t)warp * N_CLS + c] = (float)s;
    }
}

// ---------------- launch ------------------------------------------------------
extern "C" void kernel_launch(void* const* d_in, const int* in_sizes, int n_in,
                              void* d_out, int out_size) {
    const float* x     = (const float*)d_in[0];
    const float* w1    = (const float*)d_in[1];
    const float* gamma = (const float*)d_in[2];
    const float* beta  = (const float*)d_in[3];
    const float* w2    = (const float*)d_in[4];
    float* out = (float*)d_out;

    cudaFuncSetAttribute(gemm1_kernel,
                         cudaFuncAttributeMaxDynamicSharedMemorySize, NSTAGE * STAGE_B);

    prep_kernel<<<(D_H * KP + 255) / 256, 256>>>(w1, w2);
    convert_kernel<<<(int)(((size_t)B_ROWS * (D_IN / 4) + 255) / 256), 256>>>(x);
    pad_kernel<<<(B_ROWS * 2 + 255) / 256, 256>>>();

    gemm1_kernel<<<dim3(D_H / BNT, B_ROWS / BMT), 256, NSTAGE * STAGE_B>>>();

    stats_kernel<<<dim3(D_H / 256, 64), 256>>>();
    finalize_kernel<<<4, 256>>>(gamma, beta);
    out_kernel<<<(B_ROWS * 32) / 256, 256>>>(out);
}

// round 4
// speedup vs baseline: 2.0151x; 1.0366x over previous
#include <cuda_runtime.h>
#include <cuda_bf16.h>
#include <cstdint>

#define B_ROWS 65536
#define D_IN   784
#define D_H    1024
#define N_CLS  10
#define BN_EPS 1e-5f
#define KP     2368            // padded K = 3*784 (=2352) + 16 zeros
#define BK     32
#define NIT    (KP / BK)       // 74
#define BMT    128
#define BNT    128
#define SROW   40              // smem row stride in bf16 (80 bytes)
#define STAGE_B (BMT * SROW * 2 * 2)   // A + B per stage = 20480 bytes
#define NSTAGE 4

// ---------------- device scratch ---------------------------------------------
__device__ __nv_bfloat16 g_xb[(size_t)B_ROWS * KP];   // x split into 3 bf16 planes
__device__ __nv_bfloat16 g_sb[(size_t)D_H * KP];      // sign(w1) tiled 3x, bf16
__device__ float    g_h[(size_t)B_ROWS * D_H];
__device__ float    g_sum[D_H];
__device__ float    g_sumsq[D_H];
__device__ float    g_A[D_H];
__device__ float    g_Bc[D_H];
__device__ unsigned g_tbits[N_CLS][32];

// ---------------- PTX helpers -------------------------------------------------
__device__ __forceinline__ uint32_t s2u(const void* p) {
    uint32_t a;
    asm("{ .reg .u64 t; cvta.to.shared.u64 t, %1; cvt.u32.u64 %0, t; }" : "=r"(a) : "l"(p));
    return a;
}
__device__ __forceinline__ void cpa16(uint32_t s, const void* g) {
    asm volatile("cp.async.cg.shared.global [%0], [%1], 16;" :: "r"(s), "l"(g) : "memory");
}
__device__ __forceinline__ void cp_commit() {
    asm volatile("cp.async.commit_group;" ::: "memory");
}
__device__ __forceinline__ void ldm4(uint32_t* a, uint32_t addr) {
    asm volatile("ldmatrix.sync.aligned.m8n8.x4.shared.b16 {%0,%1,%2,%3}, [%4];"
                 : "=r"(a[0]), "=r"(a[1]), "=r"(a[2]), "=r"(a[3]) : "r"(addr));
}
__device__ __forceinline__ void mma16816(float* c, const uint32_t* a, const uint32_t* b) {
    asm volatile("mma.sync.aligned.m16n8k16.row.col.f32.bf16.bf16.f32 "
                 "{%0,%1,%2,%3}, {%4,%5,%6,%7}, {%8,%9}, {%0,%1,%2,%3};"
                 : "+f"(c[0]), "+f"(c[1]), "+f"(c[2]), "+f"(c[3])
                 : "r"(a[0]), "r"(a[1]), "r"(a[2]), "r"(a[3]), "r"(b[0]), "r"(b[1]));
}

// ---------------- prep: bf16 sign(w1) tiled 3x, pack w2, zero stats ----------
__global__ void prep_kernel(const float* __restrict__ w1,
                            const float* __restrict__ w2) {
    int i = blockIdx.x * blockDim.x + threadIdx.x;
    if (i < D_H * KP) {
        int n = i / KP, k = i % KP;
        float s = 0.f;
        if (k < 3 * D_IN) {
            float v = w1[n * D_IN + (k % D_IN)];
            s = (v > 0.f) ? 1.f : (v < 0.f ? -1.f : 0.f);
        }
        g_sb[i] = __float2bfloat16(s);
    }
    if (i < D_H) { g_sum[i] = 0.f; g_sumsq[i] = 0.f; }
    if (i < N_CLS * 32) {
        int c = i >> 5, g = i & 31;
        unsigned w = 0;
        #pragma unroll
        for (int l = 0; l < 32; l++) {
            float v = w2[c * D_H + g * 32 + l];
            if (v > 0.f) w |= (1u << l);
        }
        g_tbits[c][g] = w;
    }
}

// ---------------- convert: x -> 3 bf16 planes (hi/mid/lo), K-concatenated ----
__global__ void convert_kernel(const float* __restrict__ x) {
    size_t i = (size_t)blockIdx.x * blockDim.x + threadIdx.x;
    if (i >= (size_t)B_ROWS * (D_IN / 4)) return;
    size_t m = i / (D_IN / 4);
    int k4 = (int)(i % (D_IN / 4)) * 4;
    float4 v = *(const float4*)(x + m * D_IN + k4);
    float f[4] = {v.x, v.y, v.z, v.w};
    __nv_bfloat162 hi2[2], mid2[2], lo2[2];
    #pragma unroll
    for (int j = 0; j < 2; j++) {
        __nv_bfloat16 h0 = __float2bfloat16(f[2*j]);
        __nv_bfloat16 h1 = __float2bfloat16(f[2*j+1]);
        float r0 = f[2*j]   - __bfloat162float(h0);
        float r1 = f[2*j+1] - __bfloat162float(h1);
        __nv_bfloat16 m0 = __float2bfloat16(r0);
        __nv_bfloat16 m1 = __float2bfloat16(r1);
        float s0 = r0 - __bfloat162float(m0);
        float s1 = r1 - __bfloat162float(m1);
        hi2[j]  = __nv_bfloat162(h0, h1);
        mid2[j] = __nv_bfloat162(m0, m1);
        lo2[j]  = __nv_bfloat162(__float2bfloat16(s0), __float2bfloat16(s1));
    }
    __nv_bfloat162* row = (__nv_bfloat162*)(g_xb + m * KP);
    int p = k4 >> 1;
    row[p]            = hi2[0];  row[p + 1]            = hi2[1];
    row[p + D_IN/2]   = mid2[0]; row[p + D_IN/2 + 1]   = mid2[1];
    row[p + D_IN]     = lo2[0];  row[p + D_IN + 1]     = lo2[1];
}

__global__ void pad_kernel() {
    int i = blockIdx.x * blockDim.x + threadIdx.x;
    if (i < B_ROWS * 2) {
        size_t row = (size_t)(i >> 1);
        uint4 z = make_uint4(0, 0, 0, 0);
        *(uint4*)((char*)(g_xb + row * KP + 3 * D_IN) + (i & 1) * 16) = z;
    }
}

// ---------------- GEMM1 + fused BN stats -------------------------------------
// CTA tile 128x128, 8 warps (2x4), warp tile 64x32, BK=32, 4-stage cp.async,
// single __syncthreads per K-iteration. Epilogue: write h + atomic col stats.
__global__ __launch_bounds__(256)
void gemm1_kernel() {
    extern __shared__ char smem[];
    const uint32_t sb = s2u(smem);
    const int tid = threadIdx.x, wid = tid >> 5, lane = tid & 31;
    const int bn = blockIdx.x, bm = blockIdx.y;
    const int warp_m = wid >> 2, warp_n = wid & 3;     // 2 x 4

    const __nv_bfloat16* Ab = g_xb + (size_t)bm * BMT * KP;
    const __nv_bfloat16* Bb = g_sb + (size_t)bn * BNT * KP;

    auto load_stage = [&](int it, int stage) {
        uint32_t sA = sb + stage * STAGE_B;
        uint32_t sBs = sA + BMT * SROW * 2;
        int k0 = it * BK;
        #pragma unroll
        for (int j = 0; j < 2; j++) {
            int idx = tid + j * 256;                   // 0..511
            int row = idx >> 2, q = idx & 3;
            cpa16(sA + row * (SROW * 2) + q * 16,
                  (const char*)(Ab + (size_t)row * KP + k0) + q * 16);
            cpa16(sBs + row * (SROW * 2) + q * 16,
                  (const char*)(Bb + (size_t)row * KP + k0) + q * 16);
        }
        cp_commit();
    };

    float acc[4][4][4];
    #pragma unroll
    for (int i = 0; i < 4; i++)
        #pragma unroll
        for (int j = 0; j < 4; j++)
            #pragma unroll
            for (int r = 0; r < 4; r++) acc[i][j][r] = 0.f;

    load_stage(0, 0);
    load_stage(1, 1);
    load_stage(2, 2);

    for (int i = 0; i < NIT; i++) {
        asm volatile("cp.async.wait_group 2;" ::: "memory");
        __syncthreads();
        if (i + 3 < NIT) load_stage(i + 3, (i + 3) & 3);
        else cp_commit();

        uint32_t sA = sb + (i & 3) * STAGE_B;
        uint32_t sBs = sA + BMT * SROW * 2;

        #pragma unroll
        for (int ks = 0; ks < 2; ks++) {
            uint32_t afrag[4][4], bfrag[2][4];
            #pragma unroll
            for (int mt = 0; mt < 4; mt++) {
                int row = warp_m * 64 + mt * 16 + (lane & 15);
                ldm4(afrag[mt], sA + row * (SROW * 2) + ks * 32 + (lane >> 4) * 16);
            }
            #pragma unroll
            for (int np = 0; np < 2; np++) {
                int row = warp_n * 32 + np * 16 + (lane & 7) + ((lane >> 4) << 3);
                ldm4(bfrag[np], sBs + row * (SROW * 2) + ks * 32 + ((lane >> 3) & 1) * 16);
            }
            #pragma unroll
            for (int mt = 0; mt < 4; mt++)
                #pragma unroll
                for (int nt = 0; nt < 4; nt++)
                    mma16816(acc[mt][nt], afrag[mt], bfrag[nt >> 1] + (nt & 1) * 2);
        }
    }

    // ---------------- epilogue: write h + fused column stats ----------------
    float* Hb = g_h + (size_t)(bm * BMT) * D_H + bn * BNT;
    #pragma unroll
    for (int mt = 0; mt < 4; mt++) {
        int r0 = warp_m * 64 + mt * 16 + (lane >> 2);
        #pragma unroll
        for (int nt = 0; nt < 4; nt++) {
            int c = warp_n * 32 + nt * 8 + (lane & 3) * 2;
            *(float2*)(Hb + (size_t)r0 * D_H + c)       = make_float2(acc[mt][nt][0], acc[mt][nt][1]);
            *(float2*)(Hb + (size_t)(r0 + 8) * D_H + c) = make_float2(acc[mt][nt][2], acc[mt][nt][3]);
        }
    }
    // per-thread partial sums for columns c (even) and c+1 (odd), 32 rows each
    #pragma unroll
    for (int nt = 0; nt < 4; nt++) {
        float s0 = 0.f, s1 = 0.f, q0 = 0.f, q1 = 0.f;
        #pragma unroll
        for (int mt = 0; mt < 4; mt++) {
            float a0 = acc[mt][nt][0], a1 = acc[mt][nt][1];
            float a2 = acc[mt][nt][2], a3 = acc[mt][nt][3];
            s0 += a0 + a2; s1 += a1 + a3;
            q0 = fmaf(a0, a0, q0); q0 = fmaf(a2, a2, q0);
            q1 = fmaf(a1, a1, q1); q1 = fmaf(a3, a3, q1);
        }
        // reduce over the 8 lanes sharing (lane & 3)
        #pragma unroll
        for (int off = 4; off < 32; off <<= 1) {
            s0 += __shfl_xor_sync(0xffffffffu, s0, off);
            s1 += __shfl_xor_sync(0xffffffffu, s1, off);
            q0 += __shfl_xor_sync(0xffffffffu, q0, off);
            q1 += __shfl_xor_sync(0xffffffffu, q1, off);
        }
        if (lane < 4) {
            int c = bn * BNT + warp_n * 32 + nt * 8 + lane * 2;
            atomicAdd(&g_sum[c],   s0);  atomicAdd(&g_sum[c + 1],   s1);
            atomicAdd(&g_sumsq[c], q0);  atomicAdd(&g_sumsq[c + 1], q1);
        }
    }
}

__global__ void finalize_kernel(const float* __restrict__ gamma,
                                const float* __restrict__ beta) {
    int j = blockIdx.x * blockDim.x + threadIdx.x;
    if (j < D_H) {
        float mu  = g_sum[j] * (1.f / B_ROWS);
        float var = g_sumsq[j] * (1.f / B_ROWS) - mu * mu;
        float inv = rsqrtf(var + BN_EPS);
        float A   = gamma[j] * inv;
        g_A[j]  = A;
        g_Bc[j] = beta[j] - A * mu;
    }
}

// ---------------- output: sign(bn(h)) @ sign(w2)^T via xor-popcount ----------
__global__ __launch_bounds__(256)
void out_kernel(float* __restrict__ out) {
    int warp = (blockIdx.x * 256 + threadIdx.x) >> 5;
    int lane = threadIdx.x & 31;
    if (warp >= B_ROWS) return;

    const float* hrow = g_h + (size_t)warp * D_H;
    unsigned myword = 0;
    int adj[N_CLS];
    #pragma unroll
    for (int c = 0; c < N_CLS; c++) adj[c] = 0;

    for (int g = 0; g < 32; g++) {
        int col = g * 32 + lane;
        float v = fmaf(g_A[col], hrow[col], g_Bc[col]);
        unsigned w = __ballot_sync(0xffffffffu, v > 0.f);
        if (lane == g) myword = w;
        if (v == 0.f) {
            #pragma unroll
            for (int c = 0; c < N_CLS; c++)
                adj[c] += ((g_tbits[c][g] >> lane) & 1u) ? 1 : -1;
        }
    }
    #pragma unroll
    for (int c = 0; c < N_CLS; c++) {
        unsigned x = myword ^ g_tbits[c][lane];
        int s = 32 - 2 * __popc(x) + adj[c];
        s = __reduce_add_sync(0xffffffffu, s);
        if (lane == 0) out[(size_t)warp * N_CLS + c] = (float)s;
    }
}

// ---------------- launch ------------------------------------------------------
extern "C" void kernel_launch(void* const* d_in, const int* in_sizes, int n_in,
                              void* d_out, int out_size) {
    const float* x     = (const float*)d_in[0];
    const float* w1    = (const float*)d_in[1];
    const float* gamma = (const float*)d_in[2];
    const float* beta  = (const float*)d_in[3];
    const float* w2    = (const float*)d_in[4];
    float* out = (float*)d_out;

    cudaFuncSetAttribute(gemm1_kernel,
                         cudaFuncAttributeMaxDynamicSharedMemorySize, NSTAGE * STAGE_B);

    prep_kernel<<<(D_H * KP + 255) / 256, 256>>>(w1, w2);
    convert_kernel<<<(int)(((size_t)B_ROWS * (D_IN / 4) + 255) / 256), 256>>>(x);
    pad_kernel<<<(B_ROWS * 2 + 255) / 256, 256>>>();

    gemm1_kernel<<<dim3(D_H / BNT, B_ROWS / BMT), 256, NSTAGE * STAGE_B>>>();

    finalize_kernel<<<4, 256>>>(gamma, beta);
    out_kernel<<<(B_ROWS * 32) / 256, 256>>>(out);
}

// round 5
// speedup vs baseline: 2.7108x; 1.3452x over previous
#include <cuda_runtime.h>
#include <cuda_fp16.h>
#include <cstdint>

#define B_ROWS 65536
#define D_IN   784
#define D_H    1024
#define N_CLS  10
#define BN_EPS 1e-5f
#define KP     1568            // K = 2*784 (two fp16 planes), 49 * 32
#define BK     32
#define NIT    (KP / BK)       // 49
#define BMT    128
#define BNT    256
#define SROW   40              // smem row stride in fp16 (80 bytes)
#define STAGE_B ((BMT + BNT) * SROW * 2)   // 30720 bytes per stage
#define NSTAGE 4

// ---------------- device scratch ---------------------------------------------
__device__ __half g_xb[(size_t)B_ROWS * KP];   // x split into 2 fp16 planes
__device__ __half g_sb[(size_t)D_H * KP];      // sign(w1) tiled 2x, fp16
__device__ float    g_h[(size_t)B_ROWS * D_H];
__device__ float    g_sum[D_H];
__device__ float    g_sumsq[D_H];
__device__ float    g_A[D_H];
__device__ float    g_Bc[D_H];
__device__ unsigned g_tbits[N_CLS][32];

// ---------------- PTX helpers -------------------------------------------------
__device__ __forceinline__ uint32_t s2u(const void* p) {
    uint32_t a;
    asm("{ .reg .u64 t; cvta.to.shared.u64 t, %1; cvt.u32.u64 %0, t; }" : "=r"(a) : "l"(p));
    return a;
}
__device__ __forceinline__ void cpa16(uint32_t s, const void* g) {
    asm volatile("cp.async.cg.shared.global [%0], [%1], 16;" :: "r"(s), "l"(g) : "memory");
}
__device__ __forceinline__ void cp_commit() {
    asm volatile("cp.async.commit_group;" ::: "memory");
}
__device__ __forceinline__ void ldm4(uint32_t* a, uint32_t addr) {
    asm volatile("ldmatrix.sync.aligned.m8n8.x4.shared.b16 {%0,%1,%2,%3}, [%4];"
                 : "=r"(a[0]), "=r"(a[1]), "=r"(a[2]), "=r"(a[3]) : "r"(addr));
}
__device__ __forceinline__ void mma16816(float* c, const uint32_t* a, const uint32_t* b) {
    asm volatile("mma.sync.aligned.m16n8k16.row.col.f32.f16.f16.f32 "
                 "{%0,%1,%2,%3}, {%4,%5,%6,%7}, {%8,%9}, {%0,%1,%2,%3};"
                 : "+f"(c[0]), "+f"(c[1]), "+f"(c[2]), "+f"(c[3])
                 : "r"(a[0]), "r"(a[1]), "r"(a[2]), "r"(a[3]), "r"(b[0]), "r"(b[1]));
}

// ---------------- prep: fp16 sign(w1) tiled 2x, pack w2, zero stats ----------
__global__ void prep_kernel(const float* __restrict__ w1,
                            const float* __restrict__ w2) {
    int i = blockIdx.x * blockDim.x + threadIdx.x;
    if (i < D_H * KP) {
        int n = i / KP, k = i % KP;
        float v = w1[n * D_IN + (k % D_IN)];
        float s = (v > 0.f) ? 1.f : (v < 0.f ? -1.f : 0.f);
        g_sb[i] = __float2half_rn(s);
    }
    if (i < D_H) { g_sum[i] = 0.f; g_sumsq[i] = 0.f; }
    if (i < N_CLS * 32) {
        int c = i >> 5, g = i & 31;
        unsigned w = 0;
        #pragma unroll
        for (int l = 0; l < 32; l++) {
            float v = w2[c * D_H + g * 32 + l];
            if (v > 0.f) w |= (1u << l);
        }
        g_tbits[c][g] = w;
    }
}

// ---------------- convert: x -> 2 fp16 planes (hi, lo), K-concatenated -------
__global__ void convert_kernel(const float* __restrict__ x) {
    size_t i = (size_t)blockIdx.x * blockDim.x + threadIdx.x;
    if (i >= (size_t)B_ROWS * (D_IN / 4)) return;
    size_t m = i / (D_IN / 4);
    int k4 = (int)(i % (D_IN / 4)) * 4;
    float4 v = *(const float4*)(x + m * D_IN + k4);
    float f[4] = {v.x, v.y, v.z, v.w};
    __half2 hi2[2], lo2[2];
    #pragma unroll
    for (int j = 0; j < 2; j++) {
        __half h0 = __float2half_rn(f[2*j]);
        __half h1 = __float2half_rn(f[2*j+1]);
        float r0 = f[2*j]   - __half2float(h0);
        float r1 = f[2*j+1] - __half2float(h1);
        hi2[j] = __halves2half2(h0, h1);
        lo2[j] = __halves2half2(__float2half_rn(r0), __float2half_rn(r1));
    }
    __half2* row = (__half2*)(g_xb + m * KP);
    int p = k4 >> 1;
    row[p]          = hi2[0];  row[p + 1]          = hi2[1];
    row[p + D_IN/2] = lo2[0];  row[p + D_IN/2 + 1] = lo2[1];
}

// ---------------- GEMM1 + fused BN stats -------------------------------------
// CTA tile 128x256, 8 warps (2x4), warp tile 64x64, BK=32, 4-stage cp.async.
__global__ __launch_bounds__(256, 1)
void gemm1_kernel() {
    extern __shared__ char smem[];
    const uint32_t sb = s2u(smem);
    const int tid = threadIdx.x, wid = tid >> 5, lane = tid & 31;
    const int bn = blockIdx.x, bm = blockIdx.y;
    const int warp_m = wid >> 2, warp_n = wid & 3;     // 2 x 4

    const __half* Ab = g_xb + (size_t)bm * BMT * KP;
    const __half* Bb = g_sb + (size_t)bn * BNT * KP;

    // A: 128 rows x 64B, B: 256 rows x 64B -> 1536 x 16B / 256 threads = 6 each
    auto load_stage = [&](int it, int stage) {
        uint32_t sA = sb + stage * STAGE_B;
        uint32_t sBs = sA + BMT * SROW * 2;
        int k0 = it * BK;
        #pragma unroll
        for (int j = 0; j < 2; j++) {
            int idx = tid + j * 256;                   // A: 0..511
            int row = idx >> 2, q = idx & 3;
            cpa16(sA + row * (SROW * 2) + q * 16,
                  (const char*)(Ab + (size_t)row * KP + k0) + q * 16);
        }
        #pragma unroll
        for (int j = 0; j < 4; j++) {
            int idx = tid + j * 256;                   // B: 0..1023
            int row = idx >> 2, q = idx & 3;
            cpa16(sBs + row * (SROW * 2) + q * 16,
                  (const char*)(Bb + (size_t)row * KP + k0) + q * 16);
        }
        cp_commit();
    };

    float acc[4][8][4];
    #pragma unroll
    for (int i = 0; i < 4; i++)
        #pragma unroll
        for (int j = 0; j < 8; j++)
            #pragma unroll
            for (int r = 0; r < 4; r++) acc[i][j][r] = 0.f;

    load_stage(0, 0);
    load_stage(1, 1);
    load_stage(2, 2);

    for (int i = 0; i < NIT; i++) {
        asm volatile("cp.async.wait_group 2;" ::: "memory");
        __syncthreads();
        if (i + 3 < NIT) load_stage(i + 3, (i + 3) & 3);
        else cp_commit();

        uint32_t sA = sb + (i & 3) * STAGE_B;
        uint32_t sBs = sA + BMT * SROW * 2;

        #pragma unroll
        for (int ks = 0; ks < 2; ks++) {
            uint32_t afrag[4][4], bfrag[4][4];
            #pragma unroll
            for (int mt = 0; mt < 4; mt++) {
                int row = warp_m * 64 + mt * 16 + (lane & 15);
                ldm4(afrag[mt], sA + row * (SROW * 2) + ks * 32 + (lane >> 4) * 16);
            }
            #pragma unroll
            for (int np = 0; np < 4; np++) {
                int row = warp_n * 64 + np * 16 + (lane & 7) + ((lane >> 4) << 3);
                ldm4(bfrag[np], sBs + row * (SROW * 2) + ks * 32 + ((lane >> 3) & 1) * 16);
            }
            #pragma unroll
            for (int mt = 0; mt < 4; mt++)
                #pragma unroll
                for (int nt = 0; nt < 8; nt++)
                    mma16816(acc[mt][nt], afrag[mt], bfrag[nt >> 1] + (nt & 1) * 2);
        }
    }

    // ---------------- epilogue: write h + fused column stats ----------------
    float* Hb = g_h + (size_t)(bm * BMT) * D_H + bn * BNT;
    #pragma unroll
    for (int mt = 0; mt < 4; mt++) {
        int r0 = warp_m * 64 + mt * 16 + (lane >> 2);
        #pragma unroll
        for (int nt = 0; nt < 8; nt++) {
            int c = warp_n * 64 + nt * 8 + (lane & 3) * 2;
            *(float2*)(Hb + (size_t)r0 * D_H + c)       = make_float2(acc[mt][nt][0], acc[mt][nt][1]);
            *(float2*)(Hb + (size_t)(r0 + 8) * D_H + c) = make_float2(acc[mt][nt][2], acc[mt][nt][3]);
        }
    }
    #pragma unroll
    for (int nt = 0; nt < 8; nt++) {
        float s0 = 0.f, s1 = 0.f, q0 = 0.f, q1 = 0.f;
        #pragma unroll
        for (int mt = 0; mt < 4; mt++) {
            float a0 = acc[mt][nt][0], a1 = acc[mt][nt][1];
            float a2 = acc[mt][nt][2], a3 = acc[mt][nt][3];
            s0 += a0 + a2; s1 += a1 + a3;
            q0 = fmaf(a0, a0, q0); q0 = fmaf(a2, a2, q0);
            q1 = fmaf(a1, a1, q1); q1 = fmaf(a3, a3, q1);
        }
        #pragma unroll
        for (int off = 4; off < 32; off <<= 1) {
            s0 += __shfl_xor_sync(0xffffffffu, s0, off);
            s1 += __shfl_xor_sync(0xffffffffu, s1, off);
            q0 += __shfl_xor_sync(0xffffffffu, q0, off);
            q1 += __shfl_xor_sync(0xffffffffu, q1, off);
        }
        if (lane < 4) {
            int c = bn * BNT + warp_n * 64 + nt * 8 + lane * 2;
            atomicAdd(&g_sum[c],   s0);  atomicAdd(&g_sum[c + 1],   s1);
            atomicAdd(&g_sumsq[c], q0);  atomicAdd(&g_sumsq[c + 1], q1);
        }
    }
}

__global__ void finalize_kernel(const float* __restrict__ gamma,
                                const float* __restrict__ beta) {
    int j = blockIdx.x * blockDim.x + threadIdx.x;
    if (j < D_H) {
        float mu  = g_sum[j] * (1.f / B_ROWS);
        float var = g_sumsq[j] * (1.f / B_ROWS) - mu * mu;
        float inv = rsqrtf(var + BN_EPS);
        float A   = gamma[j] * inv;
        g_A[j]  = A;
        g_Bc[j] = beta[j] - A * mu;
    }
}

// ---------------- output: sign(bn(h)) @ sign(w2)^T via xor-popcount ----------
__global__ __launch_bounds__(256)
void out_kernel(float* __restrict__ out) {
    int warp = (blockIdx.x * 256 + threadIdx.x) >> 5;
    int lane = threadIdx.x & 31;
    if (warp >= B_ROWS) return;

    const float* hrow = g_h + (size_t)warp * D_H;
    unsigned myword = 0;
    int adj[N_CLS];
    #pragma unroll
    for (int c = 0; c < N_CLS; c++) adj[c] = 0;

    for (int g = 0; g < 32; g++) {
        int col = g * 32 + lane;
        float v = fmaf(g_A[col], hrow[col], g_Bc[col]);
        unsigned w = __ballot_sync(0xffffffffu, v > 0.f);
        if (lane == g) myword = w;
        if (v == 0.f) {
            #pragma unroll
            for (int c = 0; c < N_CLS; c++)
                adj[c] += ((g_tbits[c][g] >> lane) & 1u) ? 1 : -1;
        }
    }
    #pragma unroll
    for (int c = 0; c < N_CLS; c++) {
        unsigned x = myword ^ g_tbits[c][lane];
        int s = 32 - 2 * __popc(x) + adj[c];
        s = __reduce_add_sync(0xffffffffu, s);
        if (lane == 0) out[(size_t)warp * N_CLS + c] = (float)s;
    }
}

// ---------------- launch ------------------------------------------------------
extern "C" void kernel_launch(void* const* d_in, const int* in_sizes, int n_in,
                              void* d_out, int out_size) {
    const float* x     = (const float*)d_in[0];
    const float* w1    = (const float*)d_in[1];
    const float* gamma = (const float*)d_in[2];
    const float* beta  = (const float*)d_in[3];
    const float* w2    = (const float*)d_in[4];
    float* out = (float*)d_out;

    cudaFuncSetAttribute(gemm1_kernel,
                         cudaFuncAttributeMaxDynamicSharedMemorySize, NSTAGE * STAGE_B);

    prep_kernel<<<(D_H * KP + 255) / 256, 256>>>(w1, w2);
    convert_kernel<<<(int)(((size_t)B_ROWS * (D_IN / 4) + 255) / 256), 256>>>(x);

    gemm1_kernel<<<dim3(D_H / BNT, B_ROWS / BMT), 256, NSTAGE * STAGE_B>>>();

    finalize_kernel<<<4, 256>>>(gamma, beta);
    out_kernel<<<(B_ROWS * 32) / 256, 256>>>(out);
}

// round 6
// speedup vs baseline: 3.1081x; 1.1466x over previous
#include <cuda_runtime.h>
#include <cuda_fp16.h>
#include <cstdint>

#define B_ROWS 65536
#define D_IN   784
#define D_H    1024
#define N_CLS  10
#define BN_EPS 1e-5f
#define KP     1600            // 2*784 fp16 planes + 32 zero pad = 25 * 64
#define KREAL  1568
#define BK     64
#define NIT    (KP / BK)       // 25
#define BMT    128
#define BNT    128
#define SROWB  144             // smem row stride bytes (128 data + 16 pad)
#define STAGE_B ((BMT + BNT) * SROWB)  // 36864 bytes
#define NSTAGE 3

// ---------------- device scratch ---------------------------------------------
__device__ __half g_xb[(size_t)B_ROWS * KP];   // x split into 2 fp16 planes
__device__ __half g_sb[(size_t)D_H * KP];      // sign(w1) tiled 2x, fp16
__device__ float    g_h[(size_t)B_ROWS * D_H];
__device__ float    g_sum[D_H];
__device__ float    g_sumsq[D_H];
__device__ float    g_A[D_H];
__device__ float    g_Bc[D_H];
__device__ unsigned g_tbits[N_CLS][32];

// ---------------- PTX helpers -------------------------------------------------
__device__ __forceinline__ uint32_t s2u(const void* p) {
    uint32_t a;
    asm("{ .reg .u64 t; cvta.to.shared.u64 t, %1; cvt.u32.u64 %0, t; }" : "=r"(a) : "l"(p));
    return a;
}
__device__ __forceinline__ void cpa16(uint32_t s, const void* g) {
    asm volatile("cp.async.cg.shared.global [%0], [%1], 16;" :: "r"(s), "l"(g) : "memory");
}
__device__ __forceinline__ void cp_commit() {
    asm volatile("cp.async.commit_group;" ::: "memory");
}
__device__ __forceinline__ void ldm4(uint32_t* a, uint32_t addr) {
    asm volatile("ldmatrix.sync.aligned.m8n8.x4.shared.b16 {%0,%1,%2,%3}, [%4];"
                 : "=r"(a[0]), "=r"(a[1]), "=r"(a[2]), "=r"(a[3]) : "r"(addr));
}
__device__ __forceinline__ void mma16816(float* c, const uint32_t* a, const uint32_t* b) {
    asm volatile("mma.sync.aligned.m16n8k16.row.col.f32.f16.f16.f32 "
                 "{%0,%1,%2,%3}, {%4,%5,%6,%7}, {%8,%9}, {%0,%1,%2,%3};"
                 : "+f"(c[0]), "+f"(c[1]), "+f"(c[2]), "+f"(c[3])
                 : "r"(a[0]), "r"(a[1]), "r"(a[2]), "r"(a[3]), "r"(b[0]), "r"(b[1]));
}

// ---------------- prep: fp16 sign(w1) tiled 2x (zero-padded), pack w2 --------
__global__ void prep_kernel(const float* __restrict__ w1,
                            const float* __restrict__ w2) {
    int i = blockIdx.x * blockDim.x + threadIdx.x;
    if (i < D_H * KP) {
        int n = i / KP, k = i % KP;
        float s = 0.f;
        if (k < KREAL) {
            float v = w1[n * D_IN + (k % D_IN)];
            s = (v > 0.f) ? 1.f : (v < 0.f ? -1.f : 0.f);
        }
        g_sb[i] = __float2half_rn(s);
    }
    if (i < D_H) { g_sum[i] = 0.f; g_sumsq[i] = 0.f; }
    if (i < N_CLS * 32) {
        int c = i >> 5, g = i & 31;
        unsigned w = 0;
        #pragma unroll
        for (int l = 0; l < 32; l++) {
            float v = w2[c * D_H + g * 32 + l];
            if (v > 0.f) w |= (1u << l);
        }
        g_tbits[c][g] = w;
    }
}

// ---------------- convert: x -> 2 fp16 planes (hi, lo), K-concatenated -------
__global__ void convert_kernel(const float* __restrict__ x) {
    size_t i = (size_t)blockIdx.x * blockDim.x + threadIdx.x;
    if (i >= (size_t)B_ROWS * (D_IN / 4)) return;
    size_t m = i / (D_IN / 4);
    int k4 = (int)(i % (D_IN / 4)) * 4;
    float4 v = *(const float4*)(x + m * D_IN + k4);
    float f[4] = {v.x, v.y, v.z, v.w};
    __half2 hi2[2], lo2[2];
    #pragma unroll
    for (int j = 0; j < 2; j++) {
        __half h0 = __float2half_rn(f[2*j]);
        __half h1 = __float2half_rn(f[2*j+1]);
        float r0 = f[2*j]   - __half2float(h0);
        float r1 = f[2*j+1] - __half2float(h1);
        hi2[j] = __halves2half2(h0, h1);
        lo2[j] = __halves2half2(__float2half_rn(r0), __float2half_rn(r1));
    }
    __half2* row = (__half2*)(g_xb + m * KP);
    int p = k4 >> 1;
    row[p]          = hi2[0];  row[p + 1]          = hi2[1];
    row[p + D_IN/2] = lo2[0];  row[p + D_IN/2 + 1] = lo2[1];
}

// zero the K-pad region of g_xb (cols 1568..1600)
__global__ void pad_kernel() {
    int i = blockIdx.x * blockDim.x + threadIdx.x;   // B_ROWS * 4 chunks of 16B
    if (i < B_ROWS * 4) {
        size_t row = (size_t)(i >> 2);
        *(uint4*)((char*)(g_xb + row * KP + KREAL) + (i & 3) * 16) =
            make_uint4(0, 0, 0, 0);
    }
}

// ---------------- GEMM1 + fused BN stats -------------------------------------
// CTA tile 128x128, 4 warps (2x2), warp tile 64x64, BK=64, 3-stage cp.async,
// 2 CTAs/SM for barrier overlap.
__global__ __launch_bounds__(128, 2)
void gemm1_kernel() {
    extern __shared__ char smem[];
    const uint32_t sb = s2u(smem);
    const int tid = threadIdx.x, wid = tid >> 5, lane = tid & 31;
    const int bn = blockIdx.x, bm = blockIdx.y;
    const int warp_m = wid >> 1, warp_n = wid & 1;     // 2 x 2

    const __half* Ab = g_xb + (size_t)bm * BMT * KP;
    const __half* Bb = g_sb + (size_t)bn * BNT * KP;

    // per stage: A 128 rows x 128B + B 128 rows x 128B = 2048 x 16B / 128 thr
    auto load_stage = [&](int it, int stage) {
        uint32_t sA = sb + stage * STAGE_B;
        uint32_t sBs = sA + BMT * SROWB;
        int k0 = it * BK;
        #pragma unroll
        for (int j = 0; j < 8; j++) {
            int idx = tid + j * 128;                   // 0..1023
            int row = idx >> 3, q = idx & 7;
            cpa16(sA + row * SROWB + q * 16,
                  (const char*)(Ab + (size_t)row * KP + k0) + q * 16);
        }
        #pragma unroll
        for (int j = 0; j < 8; j++) {
            int idx = tid + j * 128;
            int row = idx >> 3, q = idx & 7;
            cpa16(sBs + row * SROWB + q * 16,
                  (const char*)(Bb + (size_t)row * KP + k0) + q * 16);
        }
        cp_commit();
    };

    float acc[4][8][4];
    #pragma unroll
    for (int i = 0; i < 4; i++)
        #pragma unroll
        for (int j = 0; j < 8; j++)
            #pragma unroll
            for (int r = 0; r < 4; r++) acc[i][j][r] = 0.f;

    load_stage(0, 0);
    load_stage(1, 1);

    for (int i = 0; i < NIT; i++) {
        asm volatile("cp.async.wait_group 1;" ::: "memory");
        __syncthreads();
        int nxt = i + 2;
        if (nxt < NIT) load_stage(nxt, nxt - nxt / 3 * 3);
        else cp_commit();

        uint32_t sA = sb + (i - i / 3 * 3) * STAGE_B;
        uint32_t sBs = sA + BMT * SROWB;

        #pragma unroll
        for (int ks = 0; ks < 4; ks++) {
            uint32_t afrag[4][4], bfrag[4][4];
            #pragma unroll
            for (int mt = 0; mt < 4; mt++) {
                int row = warp_m * 64 + mt * 16 + (lane & 15);
                ldm4(afrag[mt], sA + row * SROWB + ks * 32 + (lane >> 4) * 16);
            }
            #pragma unroll
            for (int np = 0; np < 4; np++) {
                int row = warp_n * 64 + np * 16 + (lane & 7) + ((lane >> 4) << 3);
                ldm4(bfrag[np], sBs + row * SROWB + ks * 32 + ((lane >> 3) & 1) * 16);
            }
            #pragma unroll
            for (int mt = 0; mt < 4; mt++)
                #pragma unroll
                for (int nt = 0; nt < 8; nt++)
                    mma16816(acc[mt][nt], afrag[mt], bfrag[nt >> 1] + (nt & 1) * 2);
        }
    }

    // ---------------- epilogue: write h + fused column stats ----------------
    float* Hb = g_h + (size_t)(bm * BMT) * D_H + bn * BNT;
    #pragma unroll
    for (int mt = 0; mt < 4; mt++) {
        int r0 = warp_m * 64 + mt * 16 + (lane >> 2);
        #pragma unroll
        for (int nt = 0; nt < 8; nt++) {
            int c = warp_n * 64 + nt * 8 + (lane & 3) * 2;
            *(float2*)(Hb + (size_t)r0 * D_H + c)       = make_float2(acc[mt][nt][0], acc[mt][nt][1]);
            *(float2*)(Hb + (size_t)(r0 + 8) * D_H + c) = make_float2(acc[mt][nt][2], acc[mt][nt][3]);
        }
    }
    #pragma unroll
    for (int nt = 0; nt < 8; nt++) {
        float s0 = 0.f, s1 = 0.f, q0 = 0.f, q1 = 0.f;
        #pragma unroll
        for (int mt = 0; mt < 4; mt++) {
            float a0 = acc[mt][nt][0], a1 = acc[mt][nt][1];
            float a2 = acc[mt][nt][2], a3 = acc[mt][nt][3];
            s0 += a0 + a2; s1 += a1 + a3;
            q0 = fmaf(a0, a0, q0); q0 = fmaf(a2, a2, q0);
            q1 = fmaf(a1, a1, q1); q1 = fmaf(a3, a3, q1);
        }
        #pragma unroll
        for (int off = 4; off < 32; off <<= 1) {
            s0 += __shfl_xor_sync(0xffffffffu, s0, off);
            s1 += __shfl_xor_sync(0xffffffffu, s1, off);
            q0 += __shfl_xor_sync(0xffffffffu, q0, off);
            q1 += __shfl_xor_sync(0xffffffffu, q1, off);
        }
        if (lane < 4) {
            int c = bn * BNT + warp_n * 64 + nt * 8 + lane * 2;
            atomicAdd(&g_sum[c],   s0);  atomicAdd(&g_sum[c + 1],   s1);
            atomicAdd(&g_sumsq[c], q0);  atomicAdd(&g_sumsq[c + 1], q1);
        }
    }
}

__global__ void finalize_kernel(const float* __restrict__ gamma,
                                const float* __restrict__ beta) {
    int j = blockIdx.x * blockDim.x + threadIdx.x;
    if (j < D_H) {
        float mu  = g_sum[j] * (1.f / B_ROWS);
        float var = g_sumsq[j] * (1.f / B_ROWS) - mu * mu;
        float inv = rsqrtf(var + BN_EPS);
        float A   = gamma[j] * inv;
        g_A[j]  = A;
        g_Bc[j] = beta[j] - A * mu;
    }
}

// ---------------- output: sign(bn(h)) @ sign(w2)^T via xor-popcount ----------
__global__ __launch_bounds__(256)
void out_kernel(float* __restrict__ out) {
    int warp = (blockIdx.x * 256 + threadIdx.x) >> 5;
    int lane = threadIdx.x & 31;
    if (warp >= B_ROWS) return;

    const float* hrow = g_h + (size_t)warp * D_H;
    unsigned myword = 0;
    int adj[N_CLS];
    #pragma unroll
    for (int c = 0; c < N_CLS; c++) adj[c] = 0;

    for (int g = 0; g < 32; g++) {
        int col = g * 32 + lane;
        float v = fmaf(g_A[col], hrow[col], g_Bc[col]);
        unsigned w = __ballot_sync(0xffffffffu, v > 0.f);
        if (lane == g) myword = w;
        if (v == 0.f) {
            #pragma unroll
            for (int c = 0; c < N_CLS; c++)
                adj[c] += ((g_tbits[c][g] >> lane) & 1u) ? 1 : -1;
        }
    }
    #pragma unroll
    for (int c = 0; c < N_CLS; c++) {
        unsigned x = myword ^ g_tbits[c][lane];
        int s = 32 - 2 * __popc(x) + adj[c];
        s = __reduce_add_sync(0xffffffffu, s);
        if (lane == 0) out[(size_t)warp * N_CLS + c] = (float)s;
    }
}

// ---------------- launch ------------------------------------------------------
extern "C" void kernel_launch(void* const* d_in, const int* in_sizes, int n_in,
                              void* d_out, int out_size) {
    const float* x     = (const float*)d_in[0];
    const float* w1    = (const float*)d_in[1];
    const float* gamma = (const float*)d_in[2];
    const float* beta  = (const float*)d_in[3];
    const float* w2    = (const float*)d_in[4];
    float* out = (float*)d_out;

    cudaFuncSetAttribute(gemm1_kernel,
                         cudaFuncAttributeMaxDynamicSharedMemorySize, NSTAGE * STAGE_B);

    prep_kernel<<<(D_H * KP + 255) / 256, 256>>>(w1, w2);
    convert_kernel<<<(int)(((size_t)B_ROWS * (D_IN / 4) + 255) / 256), 256>>>(x);
    pad_kernel<<<(B_ROWS * 4 + 255) / 256, 256>>>();

    gemm1_kernel<<<dim3(D_H / BNT, B_ROWS / BMT), 128, NSTAGE * STAGE_B>>>();

    finalize_kernel<<<4, 256>>>(gamma, beta);
    out_kernel<<<(B_ROWS * 32) / 256, 256>>>(out);
}

// round 8
// speedup vs baseline: 3.3011x; 1.0621x over previous
#include <cuda_runtime.h>
#include <cuda_fp16.h>
#include <cstdint>

#define B_ROWS 65536
#define D_IN   784
#define D_H    1024
#define N_CLS  10
#define BN_EPS 1e-5f
#define KP     1600            // 2*784 fp16 planes + 32 zero pad = 25 * 64
#define KREAL  1568
#define BK     64
#define NIT    (KP / BK)       // 25
#define BMT    128
#define BNT    128
#define SROWB  144             // smem row stride bytes (128 data + 16 pad)
#define STAGE_B ((BMT + BNT) * SROWB)  // 36864 bytes
#define NSTAGE 3

// ---------------- device scratch ---------------------------------------------
__device__ __half g_xb[(size_t)B_ROWS * KP];   // x split into 2 fp16 planes
__device__ __half g_sb[(size_t)D_H * KP];      // sign(w1) tiled 2x, fp16
__device__ float    g_h[(size_t)B_ROWS * D_H];
__device__ float    g_sum[D_H];
__device__ float    g_sumsq[D_H];
__device__ float    g_A[D_H];
__device__ float    g_Bc[D_H];
__device__ unsigned g_tbits[N_CLS][32];

// ---------------- PTX helpers -------------------------------------------------
__device__ __forceinline__ uint32_t s2u(const void* p) {
    uint32_t a;
    asm("{ .reg .u64 t; cvta.to.shared.u64 t, %1; cvt.u32.u64 %0, t; }" : "=r"(a) : "l"(p));
    return a;
}
__device__ __forceinline__ void cpa16(uint32_t s, const void* g) {
    asm volatile("cp.async.cg.shared.global [%0], [%1], 16;" :: "r"(s), "l"(g) : "memory");
}
__device__ __forceinline__ void cp_commit() {
    asm volatile("cp.async.commit_group;" ::: "memory");
}
__device__ __forceinline__ void ldm4(uint32_t* a, uint32_t addr) {
    asm volatile("ldmatrix.sync.aligned.m8n8.x4.shared.b16 {%0,%1,%2,%3}, [%4];"
                 : "=r"(a[0]), "=r"(a[1]), "=r"(a[2]), "=r"(a[3]) : "r"(addr));
}
__device__ __forceinline__ void mma16816(float* c, const uint32_t* a, const uint32_t* b) {
    asm volatile("mma.sync.aligned.m16n8k16.row.col.f32.f16.f16.f32 "
                 "{%0,%1,%2,%3}, {%4,%5,%6,%7}, {%8,%9}, {%0,%1,%2,%3};"
                 : "+f"(c[0]), "+f"(c[1]), "+f"(c[2]), "+f"(c[3])
                 : "r"(a[0]), "r"(a[1]), "r"(a[2]), "r"(a[3]), "r"(b[0]), "r"(b[1]));
}

// ---------------- prep: fp16 sign(w1) tiled 2x (zero-padded), pack w2 --------
__global__ void prep_kernel(const float* __restrict__ w1,
                            const float* __restrict__ w2) {
    int i = blockIdx.x * blockDim.x + threadIdx.x;
    if (i < D_H * KP) {
        int n = i / KP, k = i % KP;
        float s = 0.f;
        if (k < KREAL) {
            float v = w1[n * D_IN + (k % D_IN)];
            s = (v > 0.f) ? 1.f : (v < 0.f ? -1.f : 0.f);
        }
        g_sb[i] = __float2half_rn(s);
    }
    if (i < D_H) { g_sum[i] = 0.f; g_sumsq[i] = 0.f; }
    if (i < N_CLS * 32) {
        int c = i >> 5, g = i & 31;
        unsigned w = 0;
        #pragma unroll
        for (int l = 0; l < 32; l++) {
            float v = w2[c * D_H + g * 32 + l];
            if (v > 0.f) w |= (1u << l);
        }
        g_tbits[c][g] = w;
    }
}

// ---------------- convert: x -> 2 fp16 planes (hi, lo), K-concatenated -------
__global__ void convert_kernel(const float* __restrict__ x) {
    size_t i = (size_t)blockIdx.x * blockDim.x + threadIdx.x;
    if (i >= (size_t)B_ROWS * (D_IN / 4)) return;
    size_t m = i / (D_IN / 4);
    int k4 = (int)(i % (D_IN / 4)) * 4;
    float4 v = *(const float4*)(x + m * D_IN + k4);
    float f[4] = {v.x, v.y, v.z, v.w};
    __half2 hi2[2], lo2[2];
    #pragma unroll
    for (int j = 0; j < 2; j++) {
        __half h0 = __float2half_rn(f[2*j]);
        __half h1 = __float2half_rn(f[2*j+1]);
        float r0 = f[2*j]   - __half2float(h0);
        float r1 = f[2*j+1] - __half2float(h1);
        hi2[j] = __halves2half2(h0, h1);
        lo2[j] = __halves2half2(__float2half_rn(r0), __float2half_rn(r1));
    }
    __half2* row = (__half2*)(g_xb + m * KP);
    int p = k4 >> 1;
    row[p]          = hi2[0];  row[p + 1]          = hi2[1];
    row[p + D_IN/2] = lo2[0];  row[p + D_IN/2 + 1] = lo2[1];
}

// zero the K-pad region of g_xb (cols 1568..1600)
__global__ void pad_kernel() {
    int i = blockIdx.x * blockDim.x + threadIdx.x;   // B_ROWS * 4 chunks of 16B
    if (i < B_ROWS * 4) {
        size_t row = (size_t)(i >> 2);
        *(uint4*)((char*)(g_xb + row * KP + KREAL) + (i & 3) * 16) =
            make_uint4(0, 0, 0, 0);
    }
}

// ---------------- GEMM1 + fused BN stats -------------------------------------
// CTA tile 128x128, 4 warps (2x2), warp tile 64x64, BK=64, 3-stage cp.async,
// 2 CTAs/SM, register-stage fragment double-buffering.
__global__ __launch_bounds__(128, 2)
void gemm1_kernel() {
    extern __shared__ char smem[];
    const uint32_t sb = s2u(smem);
    const int tid = threadIdx.x, wid = tid >> 5, lane = tid & 31;
    const int bn = blockIdx.x, bm = blockIdx.y;
    const int warp_m = wid >> 1, warp_n = wid & 1;     // 2 x 2

    const __half* Ab = g_xb + (size_t)bm * BMT * KP;
    const __half* Bb = g_sb + (size_t)bn * BNT * KP;

    auto load_stage = [&](int it, int stage) {
        uint32_t sA = sb + stage * STAGE_B;
        uint32_t sBs = sA + BMT * SROWB;
        int k0 = it * BK;
        #pragma unroll
        for (int j = 0; j < 8; j++) {
            int idx = tid + j * 128;
            int row = idx >> 3, q = idx & 7;
            cpa16(sA + row * SROWB + q * 16,
                  (const char*)(Ab + (size_t)row * KP + k0) + q * 16);
        }
        #pragma unroll
        for (int j = 0; j < 8; j++) {
            int idx = tid + j * 128;
            int row = idx >> 3, q = idx & 7;
            cpa16(sBs + row * SROWB + q * 16,
                  (const char*)(Bb + (size_t)row * KP + k0) + q * 16);
        }
        cp_commit();
    };

    // precomputed ldmatrix intra-tile offsets
    const uint32_t a_off = (warp_m * 64 + (lane & 15)) * SROWB + (lane >> 4) * 16;
    const uint32_t b_off = (warp_n * 64 + (lane & 7) + ((lane >> 4) << 3)) * SROWB
                         + ((lane >> 3) & 1) * 16;

    float acc[4][8][4];
    #pragma unroll
    for (int i = 0; i < 4; i++)
        #pragma unroll
        for (int j = 0; j < 8; j++)
            #pragma unroll
            for (int r = 0; r < 4; r++) acc[i][j][r] = 0.f;

    load_stage(0, 0);
    load_stage(1, 1);

    uint32_t fa[2][4][4], fb[2][4][4];

    for (int i = 0; i < NIT; i++) {
        asm volatile("cp.async.wait_group 1;" ::: "memory");
        __syncthreads();
        uint32_t sA = sb + (i - i / 3 * 3) * STAGE_B;
        uint32_t sBs = sA + BMT * SROWB;

        // prefetch ks=0 fragments
        #pragma unroll
        for (int mt = 0; mt < 4; mt++)
            ldm4(fa[0][mt], sA + a_off + mt * 16 * SROWB);
        #pragma unroll
        for (int np = 0; np < 4; np++)
            ldm4(fb[0][np], sBs + b_off + np * 16 * SROWB);

        int nxt = i + 2;
        if (nxt < NIT) load_stage(nxt, nxt - nxt / 3 * 3);
        else cp_commit();

        #pragma unroll
        for (int ks = 0; ks < 4; ks++) {
            int cur = ks & 1;
            if (ks < 3) {
                int nb = cur ^ 1;
                uint32_t ko = (ks + 1) * 32;
                #pragma unroll
                for (int mt = 0; mt < 4; mt++)
                    ldm4(fa[nb][mt], sA + a_off + mt * 16 * SROWB + ko);
                #pragma unroll
                for (int np = 0; np < 4; np++)
                    ldm4(fb[nb][np], sBs + b_off + np * 16 * SROWB + ko);
            }
            #pragma unroll
            for (int mt = 0; mt < 4; mt++)
                #pragma unroll
                for (int nt = 0; nt < 8; nt++)
                    mma16816(acc[mt][nt], fa[cur][mt], fb[cur][nt >> 1] + (nt & 1) * 2);
        }
    }

    // ---------------- epilogue: write h + fused column stats ----------------
    float* Hb = g_h + (size_t)(bm * BMT) * D_H + bn * BNT;
    #pragma unroll
    for (int mt = 0; mt < 4; mt++) {
        int r0 = warp_m * 64 + mt * 16 + (lane >> 2);
        #pragma unroll
        for (int nt = 0; nt < 8; nt++) {
            int c = warp_n * 64 + nt * 8 + (lane & 3) * 2;
            *(float2*)(Hb + (size_t)r0 * D_H + c)       = make_float2(acc[mt][nt][0], acc[mt][nt][1]);
            *(float2*)(Hb + (size_t)(r0 + 8) * D_H + c) = make_float2(acc[mt][nt][2], acc[mt][nt][3]);
        }
    }
    #pragma unroll
    for (int nt = 0; nt < 8; nt++) {
        float s0 = 0.f, s1 = 0.f, q0 = 0.f, q1 = 0.f;
        #pragma unroll
        for (int mt = 0; mt < 4; mt++) {
            float a0 = acc[mt][nt][0], a1 = acc[mt][nt][1];
            float a2 = acc[mt][nt][2], a3 = acc[mt][nt][3];
            s0 += a0 + a2; s1 += a1 + a3;
            q0 = fmaf(a0, a0, q0); q0 = fmaf(a2, a2, q0);
            q1 = fmaf(a1, a1, q1); q1 = fmaf(a3, a3, q1);
        }
        #pragma unroll
        for (int off = 4; off < 32; off <<= 1) {
            s0 += __shfl_xor_sync(0xffffffffu, s0, off);
            s1 += __shfl_xor_sync(0xffffffffu, s1, off);
            q0 += __shfl_xor_sync(0xffffffffu, q0, off);
            q1 += __shfl_xor_sync(0xffffffffu, q1, off);
        }
        if (lane < 4) {
            int c = bn * BNT + warp_n * 64 + nt * 8 + lane * 2;
            atomicAdd(&g_sum[c],   s0);  atomicAdd(&g_sum[c + 1],   s1);
            atomicAdd(&g_sumsq[c], q0);  atomicAdd(&g_sumsq[c + 1], q1);
        }
    }
}

__global__ void finalize_kernel(const float* __restrict__ gamma,
                                const float* __restrict__ beta) {
    int j = blockIdx.x * blockDim.x + threadIdx.x;
    if (j < D_H) {
        float mu  = g_sum[j] * (1.f / B_ROWS);
        float var = g_sumsq[j] * (1.f / B_ROWS) - mu * mu;
        float inv = rsqrtf(var + BN_EPS);
        float A   = gamma[j] * inv;
        g_A[j]  = A;
        g_Bc[j] = beta[j] - A * mu;
    }
}

// ---------------- output: sign(bn(h)) @ sign(w2)^T via xor-popcount ----------
__global__ __launch_bounds__(256)
void out_kernel(float* __restrict__ out) {
    int warp = (blockIdx.x * 256 + threadIdx.x) >> 5;
    int lane = threadIdx.x & 31;
    if (warp >= B_ROWS) return;

    const float* hrow = g_h + (size_t)warp * D_H;
    unsigned myword = 0;
    int adj[N_CLS];
    #pragma unroll
    for (int c = 0; c < N_CLS; c++) adj[c] = 0;

    for (int g = 0; g < 32; g++) {
        int col = g * 32 + lane;
        float v = fmaf(g_A[col], hrow[col], g_Bc[col]);
        unsigned w = __ballot_sync(0xffffffffu, v > 0.f);
        if (lane == g) myword = w;
        if (v == 0.f) {
            #pragma unroll
            for (int c = 0; c < N_CLS; c++)
                adj[c] += ((g_tbits[c][g] >> lane) & 1u) ? 1 : -1;
        }
    }
    #pragma unroll
    for (int c = 0; c < N_CLS; c++) {
        unsigned x = myword ^ g_tbits[c][lane];
        int s = 32 - 2 * __popc(x) + adj[c];
        s = __reduce_add_sync(0xffffffffu, s);
        if (lane == 0) out[(size_t)warp * N_CLS + c] = (float)s;
    }
}

// ---------------- launch ------------------------------------------------------
extern "C" void kernel_launch(void* const* d_in, const int* in_sizes, int n_in,
                              void* d_out, int out_size) {
    const float* x     = (const float*)d_in[0];
    const float* w1    = (const float*)d_in[1];
    const float* gamma = (const float*)d_in[2];
    const float* beta  = (const float*)d_in[3];
    const float* w2    = (const float*)d_in[4];
    float* out = (float*)d_out;

    cudaFuncSetAttribute(gemm1_kernel,
                         cudaFuncAttributeMaxDynamicSharedMemorySize, NSTAGE * STAGE_B);

    prep_kernel<<<(D_H * KP + 255) / 256, 256>>>(w1, w2);
    convert_kernel<<<(int)(((size_t)B_ROWS * (D_IN / 4) + 255) / 256), 256>>>(x);
    pad_kernel<<<(B_ROWS * 4 + 255) / 256, 256>>>();

    gemm1_kernel<<<dim3(D_H / BNT, B_ROWS / BMT), 128, NSTAGE * STAGE_B>>>();

    finalize_kernel<<<4, 256>>>(gamma, beta);
    out_kernel<<<(B_ROWS * 32) / 256, 256>>>(out);
}